// round 3
// baseline (speedup 1.0000x reference)
#include <cuda_runtime.h>
#include <math.h>
#include <stdint.h>

// Problem dims (fixed by the reference)
#define B_   4096
#define DIN  2048
#define H_   4096
#define H1_  2048
#define H2_  1024
#define OUT_ 1000

#define CAND_MAX 32

// ---------------------------------------------------------------------------
// Scratch (device globals: allocation-free per harness rules)
// ---------------------------------------------------------------------------
__device__ float g_dist[(size_t)B_ * H_];   // 64 MB
__device__ float g_soft[(size_t)B_ * H_];   // 64 MB
__device__ float g_h1  [(size_t)B_ * H1_];  // 32 MB
__device__ float g_h2  [(size_t)B_ * H2_];  // 16 MB
__device__ float g_x2  [B_];
__device__ float g_w2  [H_];

// ---------------------------------------------------------------------------
// Row sum-of-squares: one block per row
// ---------------------------------------------------------------------------
__global__ void rownorm2_kernel(const float* __restrict__ A,
                                float* __restrict__ out, int cols) {
    const int r = blockIdx.x;
    const float* a = A + (size_t)r * cols;
    float s = 0.f;
    for (int c = threadIdx.x * 4; c < cols; c += blockDim.x * 4) {
        float4 v = *(const float4*)&a[c];
        s += v.x * v.x + v.y * v.y + v.z * v.z + v.w * v.w;
    }
    __shared__ float red[32];
    #pragma unroll
    for (int o = 16; o; o >>= 1) s += __shfl_down_sync(0xffffffffu, s, o);
    if ((threadIdx.x & 31) == 0) red[threadIdx.x >> 5] = s;
    __syncthreads();
    if (threadIdx.x < 32) {
        float t = (threadIdx.x < (blockDim.x >> 5)) ? red[threadIdx.x] : 0.f;
        #pragma unroll
        for (int o = 16; o; o >>= 1) t += __shfl_down_sync(0xffffffffu, t, o);
        if (threadIdx.x == 0) out[r] = t;
    }
}

// ---------------------------------------------------------------------------
// SGEMM-NT: C[M,N] = A[M,K] @ B[N,K]^T, with fused epilogue.
//   MODE 0: dist   -> C = sqrt(max(aux0[row] + aux1[col] - 2*acc, 1e-12))
//   MODE 1: relu   -> C = max(acc + aux0[col], 0)
//   MODE 2: linear -> C = acc + aux0[col]
// ---------------------------------------------------------------------------
template <int MODE>
__global__ __launch_bounds__(256)
void sgemm_nt_kernel(const float* __restrict__ A, const float* __restrict__ Bm,
                     float* __restrict__ C, int M, int N, int K, int ldc,
                     const float* __restrict__ aux0, const float* __restrict__ aux1) {
    __shared__ float As[16][136];
    __shared__ float Bs[16][136];

    const int tid = threadIdx.x;
    const int tx  = tid & 15;
    const int ty  = tid >> 4;
    const int row0 = blockIdx.y * 128;
    const int col0 = blockIdx.x * 128;

    const int lrow = tid >> 2;
    const int lc4  = (tid & 3) * 4;

    float acc[8][8];
    #pragma unroll
    for (int i = 0; i < 8; i++)
        #pragma unroll
        for (int j = 0; j < 8; j++) acc[i][j] = 0.f;

    const bool bok0 = (col0 + lrow)      < N;
    const bool bok1 = (col0 + lrow + 64) < N;

    for (int k0 = 0; k0 < K; k0 += 16) {
        float4 a0 = *(const float4*)&A[(size_t)(row0 + lrow)      * K + k0 + lc4];
        float4 a1 = *(const float4*)&A[(size_t)(row0 + lrow + 64) * K + k0 + lc4];
        float4 b0 = make_float4(0.f, 0.f, 0.f, 0.f);
        float4 b1 = make_float4(0.f, 0.f, 0.f, 0.f);
        if (bok0) b0 = *(const float4*)&Bm[(size_t)(col0 + lrow)      * K + k0 + lc4];
        if (bok1) b1 = *(const float4*)&Bm[(size_t)(col0 + lrow + 64) * K + k0 + lc4];

        __syncthreads();
        As[lc4 + 0][lrow] = a0.x; As[lc4 + 1][lrow] = a0.y;
        As[lc4 + 2][lrow] = a0.z; As[lc4 + 3][lrow] = a0.w;
        As[lc4 + 0][lrow + 64] = a1.x; As[lc4 + 1][lrow + 64] = a1.y;
        As[lc4 + 2][lrow + 64] = a1.z; As[lc4 + 3][lrow + 64] = a1.w;
        Bs[lc4 + 0][lrow] = b0.x; Bs[lc4 + 1][lrow] = b0.y;
        Bs[lc4 + 2][lrow] = b0.z; Bs[lc4 + 3][lrow] = b0.w;
        Bs[lc4 + 0][lrow + 64] = b1.x; Bs[lc4 + 1][lrow + 64] = b1.y;
        Bs[lc4 + 2][lrow + 64] = b1.z; Bs[lc4 + 3][lrow + 64] = b1.w;
        __syncthreads();

        #pragma unroll
        for (int k = 0; k < 16; k++) {
            float4 av0 = *(const float4*)&As[k][ty * 4];
            float4 av1 = *(const float4*)&As[k][64 + ty * 4];
            float4 bv0 = *(const float4*)&Bs[k][tx * 4];
            float4 bv1 = *(const float4*)&Bs[k][64 + tx * 4];
            float a[8] = {av0.x, av0.y, av0.z, av0.w, av1.x, av1.y, av1.z, av1.w};
            float b[8] = {bv0.x, bv0.y, bv0.z, bv0.w, bv1.x, bv1.y, bv1.z, bv1.w};
            #pragma unroll
            for (int i = 0; i < 8; i++)
                #pragma unroll
                for (int j = 0; j < 8; j++)
                    acc[i][j] = fmaf(a[i], b[j], acc[i][j]);
        }
    }

    #pragma unroll
    for (int i = 0; i < 8; i++) {
        const int r = row0 + ((i < 4) ? (ty * 4 + i) : (64 + ty * 4 + i - 4));
        #pragma unroll
        for (int j = 0; j < 8; j++) {
            const int c = col0 + ((j < 4) ? (tx * 4 + j) : (64 + tx * 4 + j - 4));
            if (c < N) {
                float v = acc[i][j];
                if (MODE == 0) {
                    float d2 = aux0[r] + aux1[c] - 2.f * v;
                    v = sqrtf(fmaxf(d2, 1e-12f));
                } else if (MODE == 1) {
                    v = fmaxf(v + aux0[c], 0.f);
                } else {
                    v = v + aux0[c];
                }
                C[(size_t)r * ldc + c] = v;
            }
        }
    }
}

// ---------------------------------------------------------------------------
// Row softmax of (-2*dist) + argmin with fp32-tie emulation.
// The reference stores d2/dist in fp32: candidates whose exact d2 differ by
// less than ~ulp merge to the same fp32 distance, and jnp.argmin then picks
// the LOWEST index. We compute exact fp64 d2 for all near-min candidates and
// apply exactly that rule: winner = lowest index within a tie window tau of
// the exact minimum; tau ~ 0.7 * max(ulp(d2), 2*dist*ulp(dist)).
// ---------------------------------------------------------------------------
__global__ __launch_bounds__(256)
void softmax_argmin_kernel(const float* __restrict__ dist,
                           const float* __restrict__ x,
                           const float* __restrict__ kw,
                           float* __restrict__ soft,
                           float* __restrict__ winners) {
    const int b = blockIdx.x;
    const float* dr = dist + (size_t)b * H_;
    __shared__ float sd[H_];
    __shared__ float rv[256];
    __shared__ int   ri[256];
    __shared__ int   cand[CAND_MAX];
    __shared__ int   ncand;
    __shared__ double dred[256];
    __shared__ double cd2[CAND_MAX];
    __shared__ int    best_idx_sh;
    const int tid = threadIdx.x;

    float lmin = 3.4e38f; int lidx = 0;
    for (int h = tid; h < H_; h += 256) {
        float v = dr[h];
        sd[h] = v;
        if (v < lmin) { lmin = v; lidx = h; }
    }
    rv[tid] = lmin; ri[tid] = lidx;
    if (tid == 0) ncand = 0;
    __syncthreads();
    for (int s = 128; s; s >>= 1) {
        if (tid < s) {
            float ov = rv[tid + s]; int oi = ri[tid + s];
            if (ov < rv[tid] || (ov == rv[tid] && oi < ri[tid])) { rv[tid] = ov; ri[tid] = oi; }
        }
        __syncthreads();
    }
    const float mind = rv[0];
    const int   widx = ri[0];
    __syncthreads();

    // --- candidate gather: anything within MARGIN of the fp32 min ---
    const float MARGIN = 5e-3f;   // dist-level; >> fp32 tie window (~3e-6)
    const float thr = mind + MARGIN;
    for (int h = tid; h < H_; h += 256) {
        if (sd[h] <= thr) {
            int p = atomicAdd(&ncand, 1);
            if (p < CAND_MAX) cand[p] = h;
        }
    }
    __syncthreads();
    int nc = ncand; if (nc > CAND_MAX) nc = CAND_MAX;

    int final_widx = widx;
    if (nc > 1 && winners != nullptr) {
        // fp64 exact squared distance per candidate (error ~1e-13)
        const float* xr = x + (size_t)b * DIN;
        for (int c = 0; c < nc; c++) {
            const int idx = cand[c];
            const float* wr = kw + (size_t)idx * DIN;
            double s = 0.0;
            for (int k = tid; k < DIN; k += 256) {
                double d = (double)xr[k] - (double)wr[k];
                s += d * d;
            }
            dred[tid] = s;
            __syncthreads();
            for (int st = 128; st; st >>= 1) {
                if (tid < st) dred[tid] += dred[tid + st];
                __syncthreads();
            }
            if (tid == 0) cd2[c] = dred[0];
            __syncthreads();
        }
        if (tid == 0) {
            // exact minimum over candidates
            double dmin = 1e300;
            for (int c = 0; c < nc; c++) if (cd2[c] < dmin) dmin = cd2[c];
            // fp32 tie window: values this close collapse to the same fp32
            // distance in the reference, and argmin then takes the lowest index
            double dd   = sqrt(fmax(dmin, 1e-12));
            double ulp_d2   = exp2(floor(log2(fmax(dmin, 1e-30))) - 23.0);
            double ulp_dist = exp2(floor(log2(fmax(dd,   1e-30))) - 23.0);
            double tau = 0.7 * fmax(ulp_d2, 2.0 * dd * ulp_dist);
            int best = 0x7fffffff;
            for (int c = 0; c < nc; c++)
                if (cd2[c] <= dmin + tau && cand[c] < best) best = cand[c];
            best_idx_sh = best;
        }
        __syncthreads();
        final_widx = best_idx_sh;
    }

    // --- softmax over -2*dist (stable: shift by min) ---
    float ls = 0.f;
    for (int h = tid; h < H_; h += 256) ls += __expf(-2.f * (sd[h] - mind));
    rv[tid] = ls;
    __syncthreads();
    for (int s = 128; s; s >>= 1) {
        if (tid < s) rv[tid] += rv[tid + s];
        __syncthreads();
    }
    const float inv = 1.f / rv[0];

    float* sr = soft + (size_t)b * H_;
    for (int h = tid; h < H_; h += 256)
        sr[h] = __expf(-2.f * (sd[h] - mind)) * inv;

    if (tid == 0 && winners != nullptr) winners[b] = (float)final_widx;
}

// ---------------------------------------------------------------------------
// Launch
// ---------------------------------------------------------------------------
extern "C" void kernel_launch(void* const* d_in, const int* in_sizes, int n_in,
                              void* d_out, int out_size) {
    const float* x  = (const float*)d_in[0];
    const float* kw = (const float*)d_in[1];
    const float* w1 = (const float*)d_in[2];
    const float* b1 = (const float*)d_in[3];
    const float* w2 = (const float*)d_in[4];
    const float* b2 = (const float*)d_in[5];
    const float* w3 = (const float*)d_in[6];
    const float* b3 = (const float*)d_in[7];
    float* out = (float*)d_out;

    float *p_dist, *p_soft, *p_h1, *p_h2, *p_x2, *p_w2;
    cudaGetSymbolAddress((void**)&p_dist, g_dist);
    cudaGetSymbolAddress((void**)&p_soft, g_soft);
    cudaGetSymbolAddress((void**)&p_h1,   g_h1);
    cudaGetSymbolAddress((void**)&p_h2,   g_h2);
    cudaGetSymbolAddress((void**)&p_x2,   g_x2);
    cudaGetSymbolAddress((void**)&p_w2,   g_w2);

    float* winners = (out_size >= B_ * OUT_ + B_) ? (out + (size_t)B_ * OUT_) : nullptr;

    rownorm2_kernel<<<B_, 256>>>(x,  p_x2, DIN);
    rownorm2_kernel<<<H_, 256>>>(kw, p_w2, DIN);

    {
        dim3 grid(H_ / 128, B_ / 128);
        sgemm_nt_kernel<0><<<grid, 256>>>(x, kw, p_dist, B_, H_, DIN, H_, p_x2, p_w2);
    }

    softmax_argmin_kernel<<<B_, 256>>>(p_dist, x, kw, p_soft, winners);

    {
        dim3 grid(H1_ / 128, B_ / 128);
        sgemm_nt_kernel<1><<<grid, 256>>>(p_soft, w1, p_h1, B_, H1_, H_, H1_, b1, nullptr);
    }
    {
        dim3 grid(H2_ / 128, B_ / 128);
        sgemm_nt_kernel<1><<<grid, 256>>>(p_h1, w2, p_h2, B_, H2_, H1_, H2_, b2, nullptr);
    }
    {
        dim3 grid((OUT_ + 127) / 128, B_ / 128);
        sgemm_nt_kernel<2><<<grid, 256>>>(p_h2, w3, out, B_, OUT_, H2_, OUT_, b3, nullptr);
    }
}

// round 7
// speedup vs baseline: 1.7725x; 1.7725x over previous
#include <cuda_runtime.h>
#include <cuda_bf16.h>
#include <math.h>
#include <stdint.h>

// Round 7 resubmit of the R6 mma.sync bf16x3 kernel (R6 bench hit the
// known-flaky "container failed twice" infra error; see post-mortem).
// Problem dims (fixed by the reference)
#define B_   4096
#define DIN  2048
#define H_   4096
#define H1_  2048
#define H2_  1024
#define OUT_ 1000
#define CAND_MAX 32

// ---------------------------------------------------------------------------
// Scratch (device globals: allocation-free per harness rules)
// ---------------------------------------------------------------------------
__device__ float g_dist[(size_t)B_ * H_];   // 64 MB
__device__ float g_x2  [B_];
__device__ float g_w2  [H_];
// bf16 hi/lo planes
__device__ __nv_bfloat16 g_xhi [(size_t)B_  * DIN], g_xlo [(size_t)B_  * DIN];
__device__ __nv_bfloat16 g_khi [(size_t)H_  * DIN], g_klo [(size_t)H_  * DIN];
__device__ __nv_bfloat16 g_shi [(size_t)B_  * H_ ], g_slo [(size_t)B_  * H_ ];
__device__ __nv_bfloat16 g_w1hi[(size_t)H1_ * H_ ], g_w1lo[(size_t)H1_ * H_ ];
__device__ __nv_bfloat16 g_h1hi[(size_t)B_  * H1_], g_h1lo[(size_t)B_  * H1_];
__device__ __nv_bfloat16 g_w2hi[(size_t)H2_ * H1_], g_w2lo[(size_t)H2_ * H1_];
__device__ __nv_bfloat16 g_h2hi[(size_t)B_  * H2_], g_h2lo[(size_t)B_  * H2_];
__device__ __nv_bfloat16 g_w3hi[(size_t)OUT_* H2_], g_w3lo[(size_t)OUT_* H2_];

// ---------------------------------------------------------------------------
// baseline-PTX helpers (sm_80-class: cp.async + ldmatrix + mma.sync) —
// all supported by compute_100 baseline PTX (no 'a' target needed).
// ---------------------------------------------------------------------------
__device__ __forceinline__ uint32_t smem_u32(const void* p) {
    uint32_t a;
    asm("{ .reg .u64 t; cvta.to.shared.u64 t, %1; cvt.u32.u64 %0, t; }" : "=r"(a) : "l"(p));
    return a;
}
#define CP_ASYNC16(sa, ga) \
    asm volatile("cp.async.cg.shared.global [%0], [%1], 16;" :: "r"(sa), "l"(ga) : "memory")
#define CP_ASYNC16Z(sa, ga, vsz) \
    asm volatile("cp.async.cg.shared.global [%0], [%1], 16, %2;" :: "r"(sa), "l"(ga), "r"(vsz) : "memory")
#define CP_COMMIT()  asm volatile("cp.async.commit_group;" ::: "memory")
#define CP_WAIT1()   asm volatile("cp.async.wait_group 1;" ::: "memory")

#define LDM4(r0, r1, r2, r3, addr)                                             \
    asm volatile("ldmatrix.sync.aligned.m8n8.x4.shared.b16 {%0,%1,%2,%3}, [%4];" \
                 : "=r"(r0), "=r"(r1), "=r"(r2), "=r"(r3) : "r"(addr))

#define MMA16816(c, a, b0, b1)                                                 \
    asm volatile("mma.sync.aligned.m16n8k16.row.col.f32.bf16.bf16.f32 "        \
                 "{%0,%1,%2,%3}, {%4,%5,%6,%7}, {%8,%9}, {%0,%1,%2,%3};"       \
                 : "+f"((c)[0]), "+f"((c)[1]), "+f"((c)[2]), "+f"((c)[3])      \
                 : "r"((a)[0]), "r"((a)[1]), "r"((a)[2]), "r"((a)[3]),         \
                   "r"(b0), "r"(b1))

// ---------------------------------------------------------------------------
// fp32 -> (hi, lo) bf16 split, vectorized by 4
// ---------------------------------------------------------------------------
__global__ void cvt_hilo_kernel(const float4* __restrict__ a,
                                __nv_bfloat162* __restrict__ hi,
                                __nv_bfloat162* __restrict__ lo, int n4) {
    int i = blockIdx.x * blockDim.x + threadIdx.x;
    if (i >= n4) return;
    float4 v = a[i];
    __nv_bfloat16 h0 = __float2bfloat16(v.x), h1 = __float2bfloat16(v.y);
    __nv_bfloat16 h2 = __float2bfloat16(v.z), h3 = __float2bfloat16(v.w);
    __nv_bfloat16 l0 = __float2bfloat16(v.x - __bfloat162float(h0));
    __nv_bfloat16 l1 = __float2bfloat16(v.y - __bfloat162float(h1));
    __nv_bfloat16 l2 = __float2bfloat16(v.z - __bfloat162float(h2));
    __nv_bfloat16 l3 = __float2bfloat16(v.w - __bfloat162float(h3));
    hi[2 * i]     = __nv_bfloat162(h0, h1);
    hi[2 * i + 1] = __nv_bfloat162(h2, h3);
    lo[2 * i]     = __nv_bfloat162(l0, l1);
    lo[2 * i + 1] = __nv_bfloat162(l2, l3);
}

// ---------------------------------------------------------------------------
// Row sum-of-squares (fp32, unchanged)
// ---------------------------------------------------------------------------
__global__ void rownorm2_kernel(const float* __restrict__ A,
                                float* __restrict__ out, int cols) {
    const int r = blockIdx.x;
    const float* a = A + (size_t)r * cols;
    float s = 0.f;
    for (int c = threadIdx.x * 4; c < cols; c += blockDim.x * 4) {
        float4 v = *(const float4*)&a[c];
        s += v.x * v.x + v.y * v.y + v.z * v.z + v.w * v.w;
    }
    __shared__ float red[32];
    #pragma unroll
    for (int o = 16; o; o >>= 1) s += __shfl_down_sync(0xffffffffu, s, o);
    if ((threadIdx.x & 31) == 0) red[threadIdx.x >> 5] = s;
    __syncthreads();
    if (threadIdx.x < 32) {
        float t = (threadIdx.x < (blockDim.x >> 5)) ? red[threadIdx.x] : 0.f;
        #pragma unroll
        for (int o = 16; o; o >>= 1) t += __shfl_down_sync(0xffffffffu, t, o);
        if (threadIdx.x == 0) out[r] = t;
    }
}

// ---------------------------------------------------------------------------
// bf16x3 GEMM-NT via mma.sync: C[M,N] = A[M,K] @ B[N,K]^T, fused epilogue.
// The hi/lo split is folded into the K loop as 3 phases over the same
// accumulators: ph0 = Ahi*Bhi, ph1 = Alo*Bhi, ph2 = Ahi*Blo  (lo*lo dropped).
//   MODE 0: Cf = sqrt(max(aux0[row] + aux1[col] - 2*acc, 1e-12))   (fp32)
//   MODE 1: v = max(acc + aux0[col], 0) -> write (Chi, Clo) bf16 planes
//   MODE 2: Cf = acc + aux0[col]                                   (fp32)
// 128x128 CTA tile, 8 warps in 2x4 (warp tile 64x32), K-tile 32,
// 3-stage cp.async pipeline. Smem rows stride 80B (16B-phase conflict-free).
// ---------------------------------------------------------------------------
#define NSTG      3
#define ASTRIDE   80
#define ATILE_B   10240                 // 128 * 80
#define STG_B     20480                 // A + B tiles
#define GSMEM_BYTES (NSTG * STG_B)      // 61440

template <int MODE>
__global__ __launch_bounds__(256)
void mma_gemm_nt(const __nv_bfloat16* __restrict__ Ahi, const __nv_bfloat16* __restrict__ Alo,
                 const __nv_bfloat16* __restrict__ Bhi, const __nv_bfloat16* __restrict__ Blo,
                 float* __restrict__ Cf,
                 __nv_bfloat16* __restrict__ Chi, __nv_bfloat16* __restrict__ Clo,
                 int N, int K, int ldc,
                 const float* __restrict__ aux0, const float* __restrict__ aux1) {
    extern __shared__ char smem[];
    const uint32_t sbase = smem_u32(smem);

    const int tid  = threadIdx.x;
    const int lane = tid & 31;
    const int wid  = tid >> 5;
    const int wm   = wid & 1;            // 2 warps along M
    const int wn   = wid >> 1;           // 4 warps along N
    const int row0 = blockIdx.y * 128;
    const int col0 = blockIdx.x * 128;
    const int warp_m = wm * 64;
    const int warp_n = wn * 32;

    // per-lane ldmatrix offsets (within a stage)
    uint32_t a_off[4][2], b_off[2][2];
    {
        const int m_in = (lane & 7) + ((lane >> 3) & 1) * 8;
        const int a_ch = (lane >> 4);             // 0/1 -> k half chunk
        #pragma unroll
        for (int mf = 0; mf < 4; mf++)
            #pragma unroll
            for (int kk = 0; kk < 2; kk++)
                a_off[mf][kk] = (uint32_t)((warp_m + mf * 16 + m_in) * ASTRIDE + (kk * 2 + a_ch) * 16);
        const int n_in = (lane & 7) + ((lane >> 4) & 1) * 8;
        const int b_ch = (lane >> 3) & 1;
        #pragma unroll
        for (int np = 0; np < 2; np++)
            #pragma unroll
            for (int kk = 0; kk < 2; kk++)
                b_off[np][kk] = (uint32_t)(ATILE_B + (warp_n + np * 16 + n_in) * ASTRIDE + (kk * 2 + b_ch) * 16);
    }

    float acc[4][4][4];
    #pragma unroll
    for (int i = 0; i < 4; i++)
        #pragma unroll
        for (int j = 0; j < 4; j++)
            #pragma unroll
            for (int q = 0; q < 4; q++) acc[i][j][q] = 0.f;

    const int KS    = K / 32;
    const int total = 3 * KS;

    // stage loader: 2x (A chunk + B chunk) 16B cp.async per thread
    auto load_stage = [&](int s) {
        const int ph = s / KS, k0 = (s % KS) * 32;
        const __nv_bfloat16* Ap = (ph == 1) ? Alo : Ahi;
        const __nv_bfloat16* Bp = (ph == 2) ? Blo : Bhi;
        const uint32_t sb = sbase + (uint32_t)(s % NSTG) * STG_B;
        #pragma unroll
        for (int j = 0; j < 2; j++) {
            const int cid = tid * 2 + j;          // 0..511
            const int r = cid >> 2, c = cid & 3;
            const __nv_bfloat16* ga = Ap + (size_t)(row0 + r) * K + k0 + c * 8;
            CP_ASYNC16(sb + (uint32_t)(r * ASTRIDE + c * 16), ga);
            const int brow = col0 + r;
            const int vsz  = (brow < N) ? 16 : 0;
            const __nv_bfloat16* gb = Bp + ((brow < N) ? ((size_t)brow * K + k0 + c * 8) : 0);
            CP_ASYNC16Z(sb + (uint32_t)(ATILE_B + r * ASTRIDE + c * 16), gb, vsz);
        }
    };

    // prologue
    load_stage(0); CP_COMMIT();
    load_stage(1); CP_COMMIT();

    for (int s = 0; s < total; s++) {
        CP_WAIT1();
        __syncthreads();
        if (s + NSTG - 1 < total) load_stage(s + NSTG - 1);
        CP_COMMIT();

        const uint32_t sb = sbase + (uint32_t)(s % NSTG) * STG_B;
        #pragma unroll
        for (int kk = 0; kk < 2; kk++) {
            uint32_t A[4][4], Bg[2][4];
            #pragma unroll
            for (int mf = 0; mf < 4; mf++)
                LDM4(A[mf][0], A[mf][1], A[mf][2], A[mf][3], sb + a_off[mf][kk]);
            #pragma unroll
            for (int np = 0; np < 2; np++)
                LDM4(Bg[np][0], Bg[np][1], Bg[np][2], Bg[np][3], sb + b_off[np][kk]);
            #pragma unroll
            for (int mf = 0; mf < 4; mf++)
                #pragma unroll
                for (int nf = 0; nf < 4; nf++) {
                    const int np = nf >> 1, hi2 = (nf & 1) * 2;
                    MMA16816(acc[mf][nf], A[mf], Bg[np][hi2], Bg[np][hi2 + 1]);
                }
        }
        __syncthreads();
    }

    // ---------------- epilogue (direct stores, guarded cols) ----------------
    const int gid = lane >> 2, tig = lane & 3;
    #pragma unroll
    for (int mf = 0; mf < 4; mf++) {
        #pragma unroll
        for (int half = 0; half < 2; half++) {
            const int m_g = row0 + warp_m + mf * 16 + gid + half * 8;
            const float auxr = (MODE == 0) ? aux0[m_g] : 0.f;
            #pragma unroll
            for (int nf = 0; nf < 4; nf++) {
                const int n_g = col0 + warp_n + nf * 8 + 2 * tig;
                #pragma unroll
                for (int e = 0; e < 2; e++) {
                    const int nc = n_g + e;
                    if (nc >= N) continue;
                    const float a = acc[mf][nf][half * 2 + e];
                    float v;
                    if (MODE == 0)      v = sqrtf(fmaxf(auxr + aux1[nc] - 2.f * a, 1e-12f));
                    else if (MODE == 1) v = fmaxf(a + aux0[nc], 0.f);
                    else                v = a + aux0[nc];
                    const size_t off = (size_t)m_g * ldc + nc;
                    if (MODE == 1) {
                        __nv_bfloat16 h = __float2bfloat16(v);
                        Chi[off] = h;
                        Clo[off] = __float2bfloat16(v - __bfloat162float(h));
                    } else {
                        Cf[off] = v;
                    }
                }
            }
        }
    }
}

// ---------------------------------------------------------------------------
// Row softmax of (-2*dist) + argmin with fp32-tie emulation (PASSED logic,
// unchanged). Writes soft as bf16 hi/lo planes for the downstream MMA.
// ---------------------------------------------------------------------------
__global__ __launch_bounds__(256)
void softmax_argmin_kernel(const float* __restrict__ dist,
                           const float* __restrict__ x,
                           const float* __restrict__ kw,
                           __nv_bfloat16* __restrict__ soft_hi,
                           __nv_bfloat16* __restrict__ soft_lo,
                           float* __restrict__ winners) {
    const int b = blockIdx.x;
    const float* dr = dist + (size_t)b * H_;
    __shared__ float sd[H_];
    __shared__ float rv[256];
    __shared__ int   ri[256];
    __shared__ int   cand[CAND_MAX];
    __shared__ int   ncand;
    __shared__ double dred[256];
    __shared__ double cd2[CAND_MAX];
    __shared__ int    best_idx_sh;
    const int tid = threadIdx.x;

    float lmin = 3.4e38f; int lidx = 0;
    for (int h = tid; h < H_; h += 256) {
        float v = dr[h];
        sd[h] = v;
        if (v < lmin) { lmin = v; lidx = h; }
    }
    rv[tid] = lmin; ri[tid] = lidx;
    if (tid == 0) ncand = 0;
    __syncthreads();
    for (int s = 128; s; s >>= 1) {
        if (tid < s) {
            float ov = rv[tid + s]; int oi = ri[tid + s];
            if (ov < rv[tid] || (ov == rv[tid] && oi < ri[tid])) { rv[tid] = ov; ri[tid] = oi; }
        }
        __syncthreads();
    }
    const float mind = rv[0];
    const int   widx = ri[0];
    __syncthreads();

    const float MARGIN = 5e-3f;
    const float thr = mind + MARGIN;
    for (int h = tid; h < H_; h += 256) {
        if (sd[h] <= thr) {
            int p = atomicAdd(&ncand, 1);
            if (p < CAND_MAX) cand[p] = h;
        }
    }
    __syncthreads();
    int nc = ncand; if (nc > CAND_MAX) nc = CAND_MAX;

    int final_widx = widx;
    if (nc > 1 && winners != nullptr) {
        const float* xr = x + (size_t)b * DIN;
        for (int c = 0; c < nc; c++) {
            const int idx = cand[c];
            const float* wr = kw + (size_t)idx * DIN;
            double s = 0.0;
            for (int k = tid; k < DIN; k += 256) {
                double d = (double)xr[k] - (double)wr[k];
                s += d * d;
            }
            dred[tid] = s;
            __syncthreads();
            for (int st = 128; st; st >>= 1) {
                if (tid < st) dred[tid] += dred[tid + st];
                __syncthreads();
            }
            if (tid == 0) cd2[c] = dred[0];
            __syncthreads();
        }
        if (tid == 0) {
            double dmin = 1e300;
            for (int c = 0; c < nc; c++) if (cd2[c] < dmin) dmin = cd2[c];
            double dd   = sqrt(fmax(dmin, 1e-12));
            double ulp_d2   = exp2(floor(log2(fmax(dmin, 1e-30))) - 23.0);
            double ulp_dist = exp2(floor(log2(fmax(dd,   1e-30))) - 23.0);
            double tau = 0.7 * fmax(ulp_d2, 2.0 * dd * ulp_dist);
            int best = 0x7fffffff;
            for (int c = 0; c < nc; c++)
                if (cd2[c] <= dmin + tau && cand[c] < best) best = cand[c];
            best_idx_sh = best;
        }
        __syncthreads();
        final_widx = best_idx_sh;
    }

    float ls = 0.f;
    for (int h = tid; h < H_; h += 256) ls += __expf(-2.f * (sd[h] - mind));
    rv[tid] = ls;
    __syncthreads();
    for (int s = 128; s; s >>= 1) {
        if (tid < s) rv[tid] += rv[tid + s];
        __syncthreads();
    }
    const float inv = 1.f / rv[0];

    __nv_bfloat16* shr = soft_hi + (size_t)b * H_;
    __nv_bfloat16* slr = soft_lo + (size_t)b * H_;
    for (int h = tid; h < H_; h += 256) {
        float v = __expf(-2.f * (sd[h] - mind)) * inv;
        __nv_bfloat16 hh = __float2bfloat16(v);
        shr[h] = hh;
        slr[h] = __float2bfloat16(v - __bfloat162float(hh));
    }

    if (tid == 0 && winners != nullptr) winners[b] = (float)final_widx;
}

// ---------------------------------------------------------------------------
// Launch
// ---------------------------------------------------------------------------
extern "C" void kernel_launch(void* const* d_in, const int* in_sizes, int n_in,
                              void* d_out, int out_size) {
    const float* x  = (const float*)d_in[0];
    const float* kw = (const float*)d_in[1];
    const float* w1 = (const float*)d_in[2];
    const float* b1 = (const float*)d_in[3];
    const float* w2 = (const float*)d_in[4];
    const float* b2 = (const float*)d_in[5];
    const float* w3 = (const float*)d_in[6];
    const float* b3 = (const float*)d_in[7];
    float* out = (float*)d_out;

    cudaFuncSetAttribute((const void*)mma_gemm_nt<0>, cudaFuncAttributeMaxDynamicSharedMemorySize, GSMEM_BYTES);
    cudaFuncSetAttribute((const void*)mma_gemm_nt<1>, cudaFuncAttributeMaxDynamicSharedMemorySize, GSMEM_BYTES);
    cudaFuncSetAttribute((const void*)mma_gemm_nt<2>, cudaFuncAttributeMaxDynamicSharedMemorySize, GSMEM_BYTES);

    float *p_dist, *p_x2, *p_w2;
    cudaGetSymbolAddress((void**)&p_dist, g_dist);
    cudaGetSymbolAddress((void**)&p_x2,   g_x2);
    cudaGetSymbolAddress((void**)&p_w2,   g_w2);
    __nv_bfloat16 *xhi, *xlo, *khi, *klo, *shi, *slo, *w1hi, *w1lo, *h1hi, *h1lo,
                  *w2hi, *w2lo, *h2hi, *h2lo, *w3hi, *w3lo;
    cudaGetSymbolAddress((void**)&xhi,  g_xhi);  cudaGetSymbolAddress((void**)&xlo,  g_xlo);
    cudaGetSymbolAddress((void**)&khi,  g_khi);  cudaGetSymbolAddress((void**)&klo,  g_klo);
    cudaGetSymbolAddress((void**)&shi,  g_shi);  cudaGetSymbolAddress((void**)&slo,  g_slo);
    cudaGetSymbolAddress((void**)&w1hi, g_w1hi); cudaGetSymbolAddress((void**)&w1lo, g_w1lo);
    cudaGetSymbolAddress((void**)&h1hi, g_h1hi); cudaGetSymbolAddress((void**)&h1lo, g_h1lo);
    cudaGetSymbolAddress((void**)&w2hi, g_w2hi); cudaGetSymbolAddress((void**)&w2lo, g_w2lo);
    cudaGetSymbolAddress((void**)&h2hi, g_h2hi); cudaGetSymbolAddress((void**)&h2lo, g_h2lo);
    cudaGetSymbolAddress((void**)&w3hi, g_w3hi); cudaGetSymbolAddress((void**)&w3lo, g_w3lo);

    float* winners = (out_size >= B_ * OUT_ + B_) ? (out + (size_t)B_ * OUT_) : nullptr;

    auto cvt = [](const float* a, __nv_bfloat16* hi, __nv_bfloat16* lo, size_t n) {
        int n4 = (int)(n / 4);
        cvt_hilo_kernel<<<(n4 + 255) / 256, 256>>>((const float4*)a,
            (__nv_bfloat162*)hi, (__nv_bfloat162*)lo, n4);
    };
    cvt(x,  xhi,  xlo,  (size_t)B_  * DIN);
    cvt(kw, khi,  klo,  (size_t)H_  * DIN);
    cvt(w1, w1hi, w1lo, (size_t)H1_ * H_);
    cvt(w2, w2hi, w2lo, (size_t)H2_ * H1_);
    cvt(w3, w3hi, w3lo, (size_t)OUT_* H2_);

    rownorm2_kernel<<<B_, 256>>>(x,  p_x2, DIN);
    rownorm2_kernel<<<H_, 256>>>(kw, p_w2, DIN);

    // dist = sqrt(max(x2 + w2 - 2 x@kw^T, 1e-12))   [4096 x 4096] K=2048
    {
        dim3 grid(H_ / 128, B_ / 128);
        mma_gemm_nt<0><<<grid, 256, GSMEM_BYTES>>>(xhi, xlo, khi, klo,
            p_dist, nullptr, nullptr, H_, DIN, H_, p_x2, p_w2);
    }

    softmax_argmin_kernel<<<B_, 256>>>(p_dist, x, kw, shi, slo, winners);

    // h1 = relu(soft @ w1^T + b1)   [4096 x 2048] K=4096
    {
        dim3 grid(H1_ / 128, B_ / 128);
        mma_gemm_nt<1><<<grid, 256, GSMEM_BYTES>>>(shi, slo, w1hi, w1lo,
            nullptr, h1hi, h1lo, H1_, H_, H1_, b1, nullptr);
    }
    // h2 = relu(h1 @ w2^T + b2)     [4096 x 1024] K=2048
    {
        dim3 grid(H2_ / 128, B_ / 128);
        mma_gemm_nt<1><<<grid, 256, GSMEM_BYTES>>>(h1hi, h1lo, w2hi, w2lo,
            nullptr, h2hi, h2lo, H2_, H1_, H2_, b2, nullptr);
    }
    // out = h2 @ w3^T + b3          [4096 x 1000] K=1024
    {
        dim3 grid((OUT_ + 127) / 128, B_ / 128);
        mma_gemm_nt<2><<<grid, 256, GSMEM_BYTES>>>(h2hi, h2lo, w3hi, w3lo,
            out, nullptr, nullptr, OUT_, H2_, OUT_, b3, nullptr);
    }
}

// round 8
// speedup vs baseline: 1.9523x; 1.1014x over previous
#include <cuda_runtime.h>
#include <cuda_bf16.h>
#include <math.h>
#include <stdint.h>

// Problem dims (fixed by the reference)
#define B_   4096
#define DIN  2048
#define H_   4096
#define H1_  2048
#define H2_  1024
#define OUT_ 1000
#define CAND_MAX 32

// ---------------------------------------------------------------------------
// Scratch (device globals: allocation-free per harness rules)
// ---------------------------------------------------------------------------
__device__ float g_dist[(size_t)B_ * H_];   // 64 MB
__device__ float g_x2  [B_];
__device__ float g_w2  [H_];
// bf16 hi/lo planes
__device__ __nv_bfloat16 g_xhi [(size_t)B_  * DIN], g_xlo [(size_t)B_  * DIN];
__device__ __nv_bfloat16 g_khi [(size_t)H_  * DIN], g_klo [(size_t)H_  * DIN];
__device__ __nv_bfloat16 g_shi [(size_t)B_  * H_ ], g_slo [(size_t)B_  * H_ ];
__device__ __nv_bfloat16 g_w1hi[(size_t)H1_ * H_ ], g_w1lo[(size_t)H1_ * H_ ];
__device__ __nv_bfloat16 g_h1hi[(size_t)B_  * H1_], g_h1lo[(size_t)B_  * H1_];
__device__ __nv_bfloat16 g_w2hi[(size_t)H2_ * H1_], g_w2lo[(size_t)H2_ * H1_];
__device__ __nv_bfloat16 g_h2hi[(size_t)B_  * H2_], g_h2lo[(size_t)B_  * H2_];
__device__ __nv_bfloat16 g_w3hi[(size_t)OUT_* H2_], g_w3lo[(size_t)OUT_* H2_];

// ---------------------------------------------------------------------------
// baseline-PTX helpers (sm_80-class: cp.async + ldmatrix + mma.sync)
// ---------------------------------------------------------------------------
__device__ __forceinline__ uint32_t smem_u32(const void* p) {
    uint32_t a;
    asm("{ .reg .u64 t; cvta.to.shared.u64 t, %1; cvt.u32.u64 %0, t; }" : "=r"(a) : "l"(p));
    return a;
}
#define CP_ASYNC16(sa, ga) \
    asm volatile("cp.async.cg.shared.global [%0], [%1], 16;" :: "r"(sa), "l"(ga) : "memory")
#define CP_ASYNC16Z(sa, ga, vsz) \
    asm volatile("cp.async.cg.shared.global [%0], [%1], 16, %2;" :: "r"(sa), "l"(ga), "r"(vsz) : "memory")
#define CP_COMMIT()  asm volatile("cp.async.commit_group;" ::: "memory")
#define CP_WAIT1()   asm volatile("cp.async.wait_group 1;" ::: "memory")

#define LDM4(r0, r1, r2, r3, addr)                                             \
    asm volatile("ldmatrix.sync.aligned.m8n8.x4.shared.b16 {%0,%1,%2,%3}, [%4];" \
                 : "=r"(r0), "=r"(r1), "=r"(r2), "=r"(r3) : "r"(addr))

#define MMA16816(c, a, b0, b1)                                                 \
    asm volatile("mma.sync.aligned.m16n8k16.row.col.f32.bf16.bf16.f32 "        \
                 "{%0,%1,%2,%3}, {%4,%5,%6,%7}, {%8,%9}, {%0,%1,%2,%3};"       \
                 : "+f"((c)[0]), "+f"((c)[1]), "+f"((c)[2]), "+f"((c)[3])      \
                 : "r"((a)[0]), "r"((a)[1]), "r"((a)[2]), "r"((a)[3]),         \
                   "r"(b0), "r"(b1))

// ---------------------------------------------------------------------------
// fp32 -> (hi, lo) bf16 split, vectorized by 4
// ---------------------------------------------------------------------------
__global__ void cvt_hilo_kernel(const float4* __restrict__ a,
                                __nv_bfloat162* __restrict__ hi,
                                __nv_bfloat162* __restrict__ lo, int n4) {
    int i = blockIdx.x * blockDim.x + threadIdx.x;
    if (i >= n4) return;
    float4 v = a[i];
    __nv_bfloat16 h0 = __float2bfloat16(v.x), h1 = __float2bfloat16(v.y);
    __nv_bfloat16 h2 = __float2bfloat16(v.z), h3 = __float2bfloat16(v.w);
    __nv_bfloat16 l0 = __float2bfloat16(v.x - __bfloat162float(h0));
    __nv_bfloat16 l1 = __float2bfloat16(v.y - __bfloat162float(h1));
    __nv_bfloat16 l2 = __float2bfloat16(v.z - __bfloat162float(h2));
    __nv_bfloat16 l3 = __float2bfloat16(v.w - __bfloat162float(h3));
    hi[2 * i]     = __nv_bfloat162(h0, h1);
    hi[2 * i + 1] = __nv_bfloat162(h2, h3);
    lo[2 * i]     = __nv_bfloat162(l0, l1);
    lo[2 * i + 1] = __nv_bfloat162(l2, l3);
}

// ---------------------------------------------------------------------------
// Row sum-of-squares (fp32, unchanged)
// ---------------------------------------------------------------------------
__global__ void rownorm2_kernel(const float* __restrict__ A,
                                float* __restrict__ out, int cols) {
    const int r = blockIdx.x;
    const float* a = A + (size_t)r * cols;
    float s = 0.f;
    for (int c = threadIdx.x * 4; c < cols; c += blockDim.x * 4) {
        float4 v = *(const float4*)&a[c];
        s += v.x * v.x + v.y * v.y + v.z * v.z + v.w * v.w;
    }
    __shared__ float red[32];
    #pragma unroll
    for (int o = 16; o; o >>= 1) s += __shfl_down_sync(0xffffffffu, s, o);
    if ((threadIdx.x & 31) == 0) red[threadIdx.x >> 5] = s;
    __syncthreads();
    if (threadIdx.x < 32) {
        float t = (threadIdx.x < (blockDim.x >> 5)) ? red[threadIdx.x] : 0.f;
        #pragma unroll
        for (int o = 16; o; o >>= 1) t += __shfl_down_sync(0xffffffffu, t, o);
        if (threadIdx.x == 0) out[r] = t;
    }
}

// ---------------------------------------------------------------------------
// bf16x3 GEMM-NT via mma.sync, fused 2-pass plane scheme:
//   pass A (stages 0..KS-1):  stage {Ahi, Alo, Bhi}; acc += Ahi*Bhi + Alo*Bhi
//   pass B (stages KS..2KS-1): stage {Ahi, Blo};      acc += Ahi*Blo
// (lo*lo term dropped; identical numerics to the R7 3-phase kernel.)
//   MODE 0: Cf = sqrt(max(aux0[row] + aux1[col] - 2*acc, 1e-12))   (fp32)
//   MODE 1: v = max(acc + aux0[col], 0) -> write (Chi, Clo) bf16 planes
//   MODE 2: Cf = acc + aux0[col]                                   (fp32)
// CTA tile 256x128, 8 warps in 4(M)x2(N) -> warp tile 64x64, K-tile 32,
// 3-stage cp.async ring, one barrier per stage. Rows stride 80B.
// ---------------------------------------------------------------------------
#define NSTG      3
#define ASTRIDE   80
#define SLOT_A0   0
#define SLOT_A1   20480                 // 256 * 80
#define SLOT_B    40960
#define STG_B     51200                 // A0 + A1 + B (128*80)
#define GSMEM_BYTES (NSTG * STG_B)      // 153600

template <int MODE>
__global__ __launch_bounds__(256, 1)
void mma_gemm_nt(const __nv_bfloat16* __restrict__ Ahi, const __nv_bfloat16* __restrict__ Alo,
                 const __nv_bfloat16* __restrict__ Bhi, const __nv_bfloat16* __restrict__ Blo,
                 float* __restrict__ Cf,
                 __nv_bfloat16* __restrict__ Chi, __nv_bfloat16* __restrict__ Clo,
                 int N, int K, int ldc,
                 const float* __restrict__ aux0, const float* __restrict__ aux1) {
    extern __shared__ char smem[];
    const uint32_t sbase = smem_u32(smem);

    const int tid  = threadIdx.x;
    const int lane = tid & 31;
    const int wid  = tid >> 5;
    const int wm   = wid >> 1;           // 4 warps along M
    const int wn   = wid & 1;            // 2 warps along N
    const int row0 = blockIdx.y * 256;
    const int col0 = blockIdx.x * 128;
    const int warp_m = wm * 64;
    const int warp_n = wn * 64;

    // per-lane ldmatrix base offsets (kk=0; kk=1 adds 32B)
    uint32_t a_off[4], b_off[4];
    {
        const int m_in = (lane & 7) + ((lane >> 3) & 1) * 8;
        const int a_ch = (lane >> 4);
        #pragma unroll
        for (int mf = 0; mf < 4; mf++)
            a_off[mf] = (uint32_t)((warp_m + mf * 16 + m_in) * ASTRIDE + a_ch * 16);
        const int n_in = (lane & 7) + ((lane >> 4) & 1) * 8;
        const int b_ch = (lane >> 3) & 1;
        #pragma unroll
        for (int np = 0; np < 4; np++)
            b_off[np] = (uint32_t)(SLOT_B + (warp_n + np * 16 + n_in) * ASTRIDE + b_ch * 16);
    }

    float acc[4][8][4];
    #pragma unroll
    for (int i = 0; i < 4; i++)
        #pragma unroll
        for (int j = 0; j < 8; j++)
            #pragma unroll
            for (int q = 0; q < 4; q++) acc[i][j][q] = 0.f;

    const int KS    = K / 32;
    const int total = 2 * KS;

    // stage loader. pass A: Ahi->A0, Alo->A1, Bhi->B. pass B: Ahi->A0, Blo->B.
    auto load_stage = [&](int s) {
        const bool passA = (s < KS);
        const int k0 = (passA ? s : s - KS) * 32;
        const uint32_t sb = sbase + (uint32_t)(s % NSTG) * STG_B;
        #pragma unroll
        for (int j = 0; j < 4; j++) {
            const int cid = j * 256 + tid;           // 0..1023
            const int r = cid >> 2, c = cid & 3;
            const size_t ga = (size_t)(row0 + r) * K + k0 + c * 8;
            CP_ASYNC16(sb + SLOT_A0 + (uint32_t)(r * ASTRIDE + c * 16), Ahi + ga);
            if (passA)
                CP_ASYNC16(sb + SLOT_A1 + (uint32_t)(r * ASTRIDE + c * 16), Alo + ga);
        }
        const __nv_bfloat16* Bp = passA ? Bhi : Blo;
        #pragma unroll
        for (int j = 0; j < 2; j++) {
            const int cid = j * 256 + tid;           // 0..511
            const int r = cid >> 2, c = cid & 3;
            const int brow = col0 + r;
            const int vsz  = (brow < N) ? 16 : 0;
            const __nv_bfloat16* gb = Bp + ((brow < N) ? ((size_t)brow * K + k0 + c * 8) : 0);
            CP_ASYNC16Z(sb + SLOT_B + (uint32_t)(r * ASTRIDE + c * 16), gb, vsz);
        }
    };

    // prologue: 2 stages in flight
    load_stage(0); CP_COMMIT();
    load_stage(1); CP_COMMIT();

    for (int s = 0; s < total; s++) {
        CP_WAIT1();
        __syncthreads();          // all warps done with buffer (s-1)%3 before refill
        if (s + 2 < total) load_stage(s + 2);
        CP_COMMIT();

        const uint32_t sb = sbase + (uint32_t)(s % NSTG) * STG_B;
        const bool passA = (s < KS);
        #pragma unroll
        for (int kk = 0; kk < 2; kk++) {
            const uint32_t kadd = (uint32_t)(kk * 32);
            uint32_t Bg[4][4], Af[4][4];
            #pragma unroll
            for (int np = 0; np < 4; np++)
                LDM4(Bg[np][0], Bg[np][1], Bg[np][2], Bg[np][3], sb + b_off[np] + kadd);
            #pragma unroll
            for (int mf = 0; mf < 4; mf++)
                LDM4(Af[mf][0], Af[mf][1], Af[mf][2], Af[mf][3], sb + SLOT_A0 + a_off[mf] + kadd);
            #pragma unroll
            for (int mf = 0; mf < 4; mf++)
                #pragma unroll
                for (int nf = 0; nf < 8; nf++) {
                    const int np = nf >> 1, hi2 = (nf & 1) * 2;
                    MMA16816(acc[mf][nf], Af[mf], Bg[np][hi2], Bg[np][hi2 + 1]);
                }
            if (passA) {
                #pragma unroll
                for (int mf = 0; mf < 4; mf++)
                    LDM4(Af[mf][0], Af[mf][1], Af[mf][2], Af[mf][3], sb + SLOT_A1 + a_off[mf] + kadd);
                #pragma unroll
                for (int mf = 0; mf < 4; mf++)
                    #pragma unroll
                    for (int nf = 0; nf < 8; nf++) {
                        const int np = nf >> 1, hi2 = (nf & 1) * 2;
                        MMA16816(acc[mf][nf], Af[mf], Bg[np][hi2], Bg[np][hi2 + 1]);
                    }
            }
        }
    }

    // ---------------- epilogue (direct stores, guarded cols) ----------------
    const int gid = lane >> 2, tig = lane & 3;
    #pragma unroll
    for (int mf = 0; mf < 4; mf++) {
        #pragma unroll
        for (int half = 0; half < 2; half++) {
            const int m_g = row0 + warp_m + mf * 16 + gid + half * 8;
            const float auxr = (MODE == 0) ? aux0[m_g] : 0.f;
            #pragma unroll
            for (int nf = 0; nf < 8; nf++) {
                const int n_g = col0 + warp_n + nf * 8 + 2 * tig;
                #pragma unroll
                for (int e = 0; e < 2; e++) {
                    const int nc = n_g + e;
                    if (nc >= N) continue;
                    const float a = acc[mf][nf][half * 2 + e];
                    float v;
                    if (MODE == 0)      v = sqrtf(fmaxf(auxr + aux1[nc] - 2.f * a, 1e-12f));
                    else if (MODE == 1) v = fmaxf(a + aux0[nc], 0.f);
                    else                v = a + aux0[nc];
                    const size_t off = (size_t)m_g * ldc + nc;
                    if (MODE == 1) {
                        __nv_bfloat16 h = __float2bfloat16(v);
                        Chi[off] = h;
                        Clo[off] = __float2bfloat16(v - __bfloat162float(h));
                    } else {
                        Cf[off] = v;
                    }
                }
            }
        }
    }
}

// ---------------------------------------------------------------------------
// Row softmax of (-2*dist) + argmin with fp32-tie emulation (PASSED logic,
// unchanged). Writes soft as bf16 hi/lo planes for the downstream MMA.
// ---------------------------------------------------------------------------
__global__ __launch_bounds__(256)
void softmax_argmin_kernel(const float* __restrict__ dist,
                           const float* __restrict__ x,
                           const float* __restrict__ kw,
                           __nv_bfloat16* __restrict__ soft_hi,
                           __nv_bfloat16* __restrict__ soft_lo,
                           float* __restrict__ winners) {
    const int b = blockIdx.x;
    const float* dr = dist + (size_t)b * H_;
    __shared__ float sd[H_];
    __shared__ float rv[256];
    __shared__ int   ri[256];
    __shared__ int   cand[CAND_MAX];
    __shared__ int   ncand;
    __shared__ double dred[256];
    __shared__ double cd2[CAND_MAX];
    __shared__ int    best_idx_sh;
    const int tid = threadIdx.x;

    float lmin = 3.4e38f; int lidx = 0;
    for (int h = tid; h < H_; h += 256) {
        float v = dr[h];
        sd[h] = v;
        if (v < lmin) { lmin = v; lidx = h; }
    }
    rv[tid] = lmin; ri[tid] = lidx;
    if (tid == 0) ncand = 0;
    __syncthreads();
    for (int s = 128; s; s >>= 1) {
        if (tid < s) {
            float ov = rv[tid + s]; int oi = ri[tid + s];
            if (ov < rv[tid] || (ov == rv[tid] && oi < ri[tid])) { rv[tid] = ov; ri[tid] = oi; }
        }
        __syncthreads();
    }
    const float mind = rv[0];
    const int   widx = ri[0];
    __syncthreads();

    const float MARGIN = 5e-3f;
    const float thr = mind + MARGIN;
    for (int h = tid; h < H_; h += 256) {
        if (sd[h] <= thr) {
            int p = atomicAdd(&ncand, 1);
            if (p < CAND_MAX) cand[p] = h;
        }
    }
    __syncthreads();
    int nc = ncand; if (nc > CAND_MAX) nc = CAND_MAX;

    int final_widx = widx;
    if (nc > 1 && winners != nullptr) {
        const float* xr = x + (size_t)b * DIN;
        for (int c = 0; c < nc; c++) {
            const int idx = cand[c];
            const float* wr = kw + (size_t)idx * DIN;
            double s = 0.0;
            for (int k = tid; k < DIN; k += 256) {
                double d = (double)xr[k] - (double)wr[k];
                s += d * d;
            }
            dred[tid] = s;
            __syncthreads();
            for (int st = 128; st; st >>= 1) {
                if (tid < st) dred[tid] += dred[tid + st];
                __syncthreads();
            }
            if (tid == 0) cd2[c] = dred[0];
            __syncthreads();
        }
        if (tid == 0) {
            double dmin = 1e300;
            for (int c = 0; c < nc; c++) if (cd2[c] < dmin) dmin = cd2[c];
            double dd   = sqrt(fmax(dmin, 1e-12));
            double ulp_d2   = exp2(floor(log2(fmax(dmin, 1e-30))) - 23.0);
            double ulp_dist = exp2(floor(log2(fmax(dd,   1e-30))) - 23.0);
            double tau = 0.7 * fmax(ulp_d2, 2.0 * dd * ulp_dist);
            int best = 0x7fffffff;
            for (int c = 0; c < nc; c++)
                if (cd2[c] <= dmin + tau && cand[c] < best) best = cand[c];
            best_idx_sh = best;
        }
        __syncthreads();
        final_widx = best_idx_sh;
    }

    float ls = 0.f;
    for (int h = tid; h < H_; h += 256) ls += __expf(-2.f * (sd[h] - mind));
    rv[tid] = ls;
    __syncthreads();
    for (int s = 128; s; s >>= 1) {
        if (tid < s) rv[tid] += rv[tid + s];
        __syncthreads();
    }
    const float inv = 1.f / rv[0];

    __nv_bfloat16* shr = soft_hi + (size_t)b * H_;
    __nv_bfloat16* slr = soft_lo + (size_t)b * H_;
    for (int h = tid; h < H_; h += 256) {
        float v = __expf(-2.f * (sd[h] - mind)) * inv;
        __nv_bfloat16 hh = __float2bfloat16(v);
        shr[h] = hh;
        slr[h] = __float2bfloat16(v - __bfloat162float(hh));
    }

    if (tid == 0 && winners != nullptr) winners[b] = (float)final_widx;
}

// ---------------------------------------------------------------------------
// Launch
// ---------------------------------------------------------------------------
extern "C" void kernel_launch(void* const* d_in, const int* in_sizes, int n_in,
                              void* d_out, int out_size) {
    const float* x  = (const float*)d_in[0];
    const float* kw = (const float*)d_in[1];
    const float* w1 = (const float*)d_in[2];
    const float* b1 = (const float*)d_in[3];
    const float* w2 = (const float*)d_in[4];
    const float* b2 = (const float*)d_in[5];
    const float* w3 = (const float*)d_in[6];
    const float* b3 = (const float*)d_in[7];
    float* out = (float*)d_out;

    cudaFuncSetAttribute((const void*)mma_gemm_nt<0>, cudaFuncAttributeMaxDynamicSharedMemorySize, GSMEM_BYTES);
    cudaFuncSetAttribute((const void*)mma_gemm_nt<1>, cudaFuncAttributeMaxDynamicSharedMemorySize, GSMEM_BYTES);
    cudaFuncSetAttribute((const void*)mma_gemm_nt<2>, cudaFuncAttributeMaxDynamicSharedMemorySize, GSMEM_BYTES);

    float *p_dist, *p_x2, *p_w2;
    cudaGetSymbolAddress((void**)&p_dist, g_dist);
    cudaGetSymbolAddress((void**)&p_x2,   g_x2);
    cudaGetSymbolAddress((void**)&p_w2,   g_w2);
    __nv_bfloat16 *xhi, *xlo, *khi, *klo, *shi, *slo, *w1hi, *w1lo, *h1hi, *h1lo,
                  *w2hi, *w2lo, *h2hi, *h2lo, *w3hi, *w3lo;
    cudaGetSymbolAddress((void**)&xhi,  g_xhi);  cudaGetSymbolAddress((void**)&xlo,  g_xlo);
    cudaGetSymbolAddress((void**)&khi,  g_khi);  cudaGetSymbolAddress((void**)&klo,  g_klo);
    cudaGetSymbolAddress((void**)&shi,  g_shi);  cudaGetSymbolAddress((void**)&slo,  g_slo);
    cudaGetSymbolAddress((void**)&w1hi, g_w1hi); cudaGetSymbolAddress((void**)&w1lo, g_w1lo);
    cudaGetSymbolAddress((void**)&h1hi, g_h1hi); cudaGetSymbolAddress((void**)&h1lo, g_h1lo);
    cudaGetSymbolAddress((void**)&w2hi, g_w2hi); cudaGetSymbolAddress((void**)&w2lo, g_w2lo);
    cudaGetSymbolAddress((void**)&h2hi, g_h2hi); cudaGetSymbolAddress((void**)&h2lo, g_h2lo);
    cudaGetSymbolAddress((void**)&w3hi, g_w3hi); cudaGetSymbolAddress((void**)&w3lo, g_w3lo);

    float* winners = (out_size >= B_ * OUT_ + B_) ? (out + (size_t)B_ * OUT_) : nullptr;

    auto cvt = [](const float* a, __nv_bfloat16* hi, __nv_bfloat16* lo, size_t n) {
        int n4 = (int)(n / 4);
        cvt_hilo_kernel<<<(n4 + 255) / 256, 256>>>((const float4*)a,
            (__nv_bfloat162*)hi, (__nv_bfloat162*)lo, n4);
    };
    cvt(x,  xhi,  xlo,  (size_t)B_  * DIN);
    cvt(kw, khi,  klo,  (size_t)H_  * DIN);
    cvt(w1, w1hi, w1lo, (size_t)H1_ * H_);
    cvt(w2, w2hi, w2lo, (size_t)H2_ * H1_);
    cvt(w3, w3hi, w3lo, (size_t)OUT_* H2_);

    rownorm2_kernel<<<B_, 256>>>(x,  p_x2, DIN);
    rownorm2_kernel<<<H_, 256>>>(kw, p_w2, DIN);

    // dist = sqrt(max(x2 + w2 - 2 x@kw^T, 1e-12))   [4096 x 4096] K=2048
    {
        dim3 grid(H_ / 128, B_ / 256);
        mma_gemm_nt<0><<<grid, 256, GSMEM_BYTES>>>(xhi, xlo, khi, klo,
            p_dist, nullptr, nullptr, H_, DIN, H_, p_x2, p_w2);
    }

    softmax_argmin_kernel<<<B_, 256>>>(p_dist, x, kw, shi, slo, winners);

    // h1 = relu(soft @ w1^T + b1)   [4096 x 2048] K=4096
    {
        dim3 grid(H1_ / 128, B_ / 256);
        mma_gemm_nt<1><<<grid, 256, GSMEM_BYTES>>>(shi, slo, w1hi, w1lo,
            nullptr, h1hi, h1lo, H1_, H_, H1_, b1, nullptr);
    }
    // h2 = relu(h1 @ w2^T + b2)     [4096 x 1024] K=2048
    {
        dim3 grid(H2_ / 128, B_ / 256);
        mma_gemm_nt<1><<<grid, 256, GSMEM_BYTES>>>(h1hi, h1lo, w2hi, w2lo,
            nullptr, h2hi, h2lo, H2_, H1_, H2_, b2, nullptr);
    }
    // out = h2 @ w3^T + b3          [4096 x 1000] K=1024
    {
        dim3 grid((OUT_ + 127) / 128, B_ / 256);
        mma_gemm_nt<2><<<grid, 256, GSMEM_BYTES>>>(h2hi, h2lo, w3hi, w3lo,
            out, nullptr, nullptr, OUT_, H2_, OUT_, b3, nullptr);
    }
}